// round 3
// baseline (speedup 1.0000x reference)
#include <cuda_runtime.h>
#include <math.h>
#include <stdint.h>

// ChamferLoss via exact pruned nearest-neighbor search.
// batch=64, k=2048 2-D points (x = cols [0,2048), y = cols [2048,4096)).
// Per (batch, direction): counting-sort both sides by x into 128 buckets,
// then each thread scans buckets outward for its 8 bucket-adjacent queries
// with an exact window bound (monotone-min proof => identical result to
// brute force, ~20x fewer candidate pairs).

#define K        2048
#define BATCH    64
#define THREADS  256
#define EPT      8             // elements per thread (2048/256)
#define NBINS    128
#define NBLOCKS  (2 * BATCH)

__device__ float g_partials[NBLOCKS];

__global__ __launch_bounds__(THREADS, 1)
void chamfer_nn_kernel(const float* __restrict__ pred,
                       const float* __restrict__ targ)
{
    const int bx    = blockIdx.x;
    const int batch = bx >> 1;
    const int dir   = bx & 1;

    const float* q_base = (dir == 0 ? pred : targ) + batch * (2 * K);
    const float* d_base = (dir == 0 ? targ : pred) + batch * (2 * K);

    __shared__ float2 shD[K];            // bucket-ordered database points (16 KB)
    __shared__ float2 shQ[K];            // bucket-ordered query points    (16 KB)
    __shared__ short  shQi[K];           // original query index            (4 KB)
    __shared__ int    cntD[NBINS], cntQ[NBINS];
    __shared__ int    offD[NBINS + 1], offQ[NBINS + 1];
    __shared__ int    curD[NBINS], curQ[NBINS];
    __shared__ float  red[THREADS];

    const int tid = threadIdx.x;

    // ---- Load both sides (coalesced), track x min/max over BOTH sides ----
    float Dx[EPT], Dy[EPT], Qx[EPT], Qy[EPT];
    float lmin = INFINITY, lmax = -INFINITY;
    #pragma unroll
    for (int r = 0; r < EPT; ++r) {
        int j = r * THREADS + tid;
        Dx[r] = d_base[j];  Dy[r] = d_base[j + K];
        Qx[r] = q_base[j];  Qy[r] = q_base[j + K];
        lmin = fminf(lmin, fminf(Dx[r], Qx[r]));
        lmax = fmaxf(lmax, fmaxf(Dx[r], Qx[r]));
    }
    red[tid] = lmin; __syncthreads();
    for (int o = THREADS / 2; o > 0; o >>= 1) {
        if (tid < o) red[tid] = fminf(red[tid], red[tid + o]);
        __syncthreads();
    }
    float xmin = red[0]; __syncthreads();
    red[tid] = lmax; __syncthreads();
    for (int o = THREADS / 2; o > 0; o >>= 1) {
        if (tid < o) red[tid] = fmaxf(red[tid], red[tid + o]);
        __syncthreads();
    }
    float xmax = red[0]; __syncthreads();

    float range = xmax - xmin;
    float inv   = (float)NBINS / (range * 1.000001f + 1e-30f);
    float w     = 1.0f / inv;

    // ---- Histogram by x-bucket ----
    if (tid < NBINS) { cntD[tid] = 0; cntQ[tid] = 0; }
    __syncthreads();
    int bD[EPT], bQ[EPT];
    #pragma unroll
    for (int r = 0; r < EPT; ++r) {
        int b = (int)((Dx[r] - xmin) * inv);
        b = min(NBINS - 1, max(0, b)); bD[r] = b;
        atomicAdd(&cntD[b], 1);
        b = (int)((Qx[r] - xmin) * inv);
        b = min(NBINS - 1, max(0, b)); bQ[r] = b;
        atomicAdd(&cntQ[b], 1);
    }
    __syncthreads();

    // ---- Exclusive prefix (warp 0: D, warp 1: Q) ----
    int warp = tid >> 5, lane = tid & 31;
    if (warp < 2) {
        int* cnt = (warp == 0) ? cntD : cntQ;
        int* off = (warp == 0) ? offD : offQ;
        int* cur = (warp == 0) ? curD : curQ;
        int c0 = cnt[lane * 4 + 0], c1 = cnt[lane * 4 + 1];
        int c2 = cnt[lane * 4 + 2], c3 = cnt[lane * 4 + 3];
        int s = c0 + c1 + c2 + c3, e = s;
        #pragma unroll
        for (int o = 1; o < 32; o <<= 1) {
            int n = __shfl_up_sync(0xFFFFFFFF, e, o);
            if (lane >= o) e += n;
        }
        int excl = e - s;
        off[lane * 4 + 0] = excl;
        off[lane * 4 + 1] = excl + c0;
        off[lane * 4 + 2] = excl + c0 + c1;
        off[lane * 4 + 3] = excl + c0 + c1 + c2;
        cur[lane * 4 + 0] = excl;
        cur[lane * 4 + 1] = excl + c0;
        cur[lane * 4 + 2] = excl + c0 + c1;
        cur[lane * 4 + 3] = excl + c0 + c1 + c2;
        if (lane == 31) off[NBINS] = e;   // = K
    }
    __syncthreads();

    // ---- Scatter into bucket order ----
    #pragma unroll
    for (int r = 0; r < EPT; ++r) {
        int p = atomicAdd(&curD[bD[r]], 1);
        shD[p] = make_float2(Dx[r], Dy[r]);
        p = atomicAdd(&curQ[bQ[r]], 1);
        shQ[p] = make_float2(Qx[r], Qy[r]);
        shQi[p] = (short)(r * THREADS + tid);
    }
    __syncthreads();

    // ---- Scan: 8 consecutive bucket-ordered queries per thread ----
    float gqx[EPT], gqy[EPT], mn[EPT];
    short gqi[EPT];
    const int base = tid * EPT;
    float gxmin = INFINITY, gxmax = -INFINITY;
    #pragma unroll
    for (int i = 0; i < EPT; ++i) {
        float2 q = shQ[base + i];
        gqx[i] = q.x; gqy[i] = q.y;
        gqi[i] = shQi[base + i];
        mn[i] = INFINITY;
        gxmin = fminf(gxmin, q.x);
        gxmax = fmaxf(gxmax, q.x);
    }
    int bl = min(NBINS - 1, max(0, (int)((gxmin - xmin) * inv)));
    int br = min(NBINS - 1, max(0, (int)((gxmax - xmin) * inv)));

    // Initial buckets spanned by the group
    for (int b = bl; b <= br; ++b) {
        for (int idx = offD[b]; idx < offD[b + 1]; ++idx) {
            float2 t = shD[idx];
            #pragma unroll
            for (int i = 0; i < EPT; ++i) {
                float ddx = gqx[i] - t.x;
                float ddy = gqy[i] - t.y;
                float d2  = fmaf(ddx, ddx, ddy * ddy);
                mn[i] = fminf(mn[i], d2);
            }
        }
    }

    // Outward expansion with exact termination bound
    int l = bl - 1, r = br + 1;
    for (;;) {
        float m2 = mn[0];
        #pragma unroll
        for (int i = 1; i < EPT; ++i) m2 = fmaxf(m2, mn[i]);

        bool goL = false, goR = false;
        if (l >= 0) {
            float e  = xmin + (float)(l + 1) * w;  // right edge of bucket l
            float dd = gxmin - e;
            goL = (dd < 0.0f) || (dd * dd < m2);
        }
        if (r < NBINS) {
            float e  = xmin + (float)r * w;        // left edge of bucket r
            float dd = e - gxmax;
            goR = (dd < 0.0f) || (dd * dd < m2);
        }
        if (!goL && !goR) break;

        if (goL) {
            for (int idx = offD[l]; idx < offD[l + 1]; ++idx) {
                float2 t = shD[idx];
                #pragma unroll
                for (int i = 0; i < EPT; ++i) {
                    float ddx = gqx[i] - t.x;
                    float ddy = gqy[i] - t.y;
                    float d2  = fmaf(ddx, ddx, ddy * ddy);
                    mn[i] = fminf(mn[i], d2);
                }
            }
            --l;
        }
        if (goR) {
            for (int idx = offD[r]; idx < offD[r + 1]; ++idx) {
                float2 t = shD[idx];
                #pragma unroll
                for (int i = 0; i < EPT; ++i) {
                    float ddx = gqx[i] - t.x;
                    float ddy = gqy[i] - t.y;
                    float d2  = fmaf(ddx, ddx, ddy * ddy);
                    mn[i] = fminf(mn[i], d2);
                }
            }
            ++r;
        }
    }
    __syncthreads();   // all scans done before reusing shD

    // ---- Write results back by ORIGINAL index (deterministic sum order) ----
    float* rslt = (float*)shD;   // 2048 floats, reuse of 16 KB region
    #pragma unroll
    for (int i = 0; i < EPT; ++i)
        rslt[gqi[i]] = sqrtf(mn[i]);
    __syncthreads();

    float s = 0.0f;
    #pragma unroll
    for (int rr = 0; rr < EPT; ++rr)
        s += rslt[tid + rr * THREADS];

    red[tid] = s; __syncthreads();
    for (int o = THREADS / 2; o >= 32; o >>= 1) {
        if (tid < o) red[tid] += red[tid + o];
        __syncthreads();
    }
    if (tid < 32) {
        float v = red[tid];
        #pragma unroll
        for (int o = 16; o > 0; o >>= 1)
            v += __shfl_down_sync(0xFFFFFFFF, v, o);
        if (tid == 0) g_partials[bx] = v;
    }
}

__global__ void chamfer_finalize_kernel(float* __restrict__ out)
{
    int lane = threadIdx.x;
    float v = 0.0f;
    #pragma unroll
    for (int i = 0; i < NBLOCKS / 32; ++i)
        v += g_partials[i * 32 + lane];
    #pragma unroll
    for (int o = 16; o > 0; o >>= 1)
        v += __shfl_down_sync(0xFFFFFFFF, v, o);
    if (lane == 0)
        out[0] = v * (1.0f / ((float)K * (float)BATCH));
}

extern "C" void kernel_launch(void* const* d_in, const int* in_sizes, int n_in,
                              void* d_out, int out_size)
{
    const float* pred = (const float*)d_in[0];
    const float* targ = (const float*)d_in[1];
    float* out = (float*)d_out;

    chamfer_nn_kernel<<<NBLOCKS, THREADS>>>(pred, targ);
    chamfer_finalize_kernel<<<1, 32>>>(out);
}

// round 4
// speedup vs baseline: 1.6309x; 1.6309x over previous
#include <cuda_runtime.h>
#include <math.h>
#include <stdint.h>

// ChamferLoss via exact pruned NN, warp-uniform windows.
// batch=64, k=2048 2-D points (x = cols [0,2048), y = cols [2048,4096)).
// Per (batch,dir) block: counting-sort both sides by x (128 buckets); each warp
// handles 32 consecutive sorted queries; phase-1 scans the warp's own bucket
// neighborhood (broadcast LDS) to get an upper bound, phase-2 rescans the exact
// covering window. Results are bit-identical to brute force (min over a proven
// covering superset). Deterministic: results written by original index, summed
// in fixed order; finalize fused via last-block-done.

#define K        2048
#define BATCH    64
#define THREADS  256
#define EPT      8
#define NBINS    128
#define NBLOCKS  (2 * BATCH)

__device__ float g_partials[NBLOCKS];
__device__ unsigned int g_count = 0;

__global__ __launch_bounds__(THREADS, 1)
void chamfer_nn_kernel(const float* __restrict__ pred,
                       const float* __restrict__ targ,
                       float* __restrict__ out)
{
    const int bx    = blockIdx.x;
    const int batch = bx >> 1;
    const int dir   = bx & 1;

    const float* q_base = (dir == 0 ? pred : targ) + batch * (2 * K);
    const float* d_base = (dir == 0 ? targ : pred) + batch * (2 * K);

    __shared__ float2 shDxy[K];          // sorted database (x,y)      16 KB
    __shared__ float  shDz [K];          // x^2+y^2                     8 KB
    __shared__ float2 shQ  [K];          // sorted queries (x,y)       16 KB
    __shared__ short  shQi [K];          // original query index        4 KB
    __shared__ int    cntD[NBINS], cntQ[NBINS];        // reused as cursors
    __shared__ int    offD[NBINS + 1], offQ[NBINS + 1];
    __shared__ float  red[THREADS];
    __shared__ int    lastflag;

    const int tid = threadIdx.x;

    // ---- Load both sides (coalesced); global x min/max over BOTH sides ----
    float Dx[EPT], Dy[EPT], Qx[EPT], Qy[EPT];
    float lmin = INFINITY, lmax = -INFINITY;
    #pragma unroll
    for (int r = 0; r < EPT; ++r) {
        int j = r * THREADS + tid;
        Dx[r] = d_base[j];  Dy[r] = d_base[j + K];
        Qx[r] = q_base[j];  Qy[r] = q_base[j + K];
        lmin = fminf(lmin, fminf(Dx[r], Qx[r]));
        lmax = fmaxf(lmax, fmaxf(Dx[r], Qx[r]));
    }
    red[tid] = lmin; __syncthreads();
    for (int o = THREADS / 2; o > 0; o >>= 1) {
        if (tid < o) red[tid] = fminf(red[tid], red[tid + o]);
        __syncthreads();
    }
    const float xmin = red[0]; __syncthreads();
    red[tid] = lmax; __syncthreads();
    for (int o = THREADS / 2; o > 0; o >>= 1) {
        if (tid < o) red[tid] = fmaxf(red[tid], red[tid + o]);
        __syncthreads();
    }
    const float xmax = red[0]; __syncthreads();

    const float inv = (float)NBINS / ((xmax - xmin) * 1.000001f + 1e-30f);
    const float w   = 1.0f / inv;

    // ---- Histograms ----
    if (tid < NBINS) { cntD[tid] = 0; cntQ[tid] = 0; }
    __syncthreads();
    int bD[EPT], bQ[EPT];
    #pragma unroll
    for (int r = 0; r < EPT; ++r) {
        int b = (int)((Dx[r] - xmin) * inv);
        bD[r] = min(NBINS - 1, max(0, b));
        atomicAdd(&cntD[bD[r]], 1);
        b = (int)((Qx[r] - xmin) * inv);
        bQ[r] = min(NBINS - 1, max(0, b));
        atomicAdd(&cntQ[bQ[r]], 1);
    }
    __syncthreads();

    // ---- Exclusive prefix (warp 0: D, warp 1: Q); cnt arrays become cursors ----
    int warp = tid >> 5, lane = tid & 31;
    if (warp < 2) {
        int* cnt = (warp == 0) ? cntD : cntQ;
        int* off = (warp == 0) ? offD : offQ;
        int c0 = cnt[lane * 4 + 0], c1 = cnt[lane * 4 + 1];
        int c2 = cnt[lane * 4 + 2], c3 = cnt[lane * 4 + 3];
        int s = c0 + c1 + c2 + c3, e = s;
        #pragma unroll
        for (int o = 1; o < 32; o <<= 1) {
            int n = __shfl_up_sync(0xFFFFFFFF, e, o);
            if (lane >= o) e += n;
        }
        int excl = e - s;
        off[lane * 4 + 0] = excl;
        off[lane * 4 + 1] = excl + c0;
        off[lane * 4 + 2] = excl + c0 + c1;
        off[lane * 4 + 3] = excl + c0 + c1 + c2;
        cnt[lane * 4 + 0] = excl;
        cnt[lane * 4 + 1] = excl + c0;
        cnt[lane * 4 + 2] = excl + c0 + c1;
        cnt[lane * 4 + 3] = excl + c0 + c1 + c2;
        if (lane == 31) off[NBINS] = e;
    }
    __syncthreads();

    // ---- Scatter into bucket order ----
    #pragma unroll
    for (int r = 0; r < EPT; ++r) {
        int p = atomicAdd(&cntD[bD[r]], 1);
        shDxy[p] = make_float2(Dx[r], Dy[r]);
        shDz[p]  = fmaf(Dx[r], Dx[r], Dy[r] * Dy[r]);
        p = atomicAdd(&cntQ[bQ[r]], 1);
        shQ[p]  = make_float2(Qx[r], Qy[r]);
        shQi[p] = (short)(r * THREADS + tid);
    }
    __syncthreads();

    // ---- Chunks: each warp takes 32 consecutive sorted queries ----
    for (int c = 0; c < EPT; ++c) {
        const int qs = c * THREADS + tid;
        const float2 q = shQ[qs];
        const float ax = -2.0f * q.x;
        const float ay = -2.0f * q.y;
        const float q2 = fmaf(q.x, q.x, q.y * q.y);

        int b = min(NBINS - 1, max(0, (int)((q.x - xmin) * inv)));
        int bl = b, bh = b;
        #pragma unroll
        for (int o = 16; o > 0; o >>= 1) {
            bl = min(bl, __shfl_xor_sync(0xFFFFFFFF, bl, o));
            bh = max(bh, __shfl_xor_sync(0xFFFFFFFF, bh, o));
        }

        // Phase 1: warp-uniform neighborhood scan -> per-query upper bound
        float mn = INFINITY;
        {
            const int lo = offD[max(bl - 1, 0)];
            const int hi = offD[min(bh + 1, NBINS - 1) + 1];
            for (int idx = lo; idx < hi; ++idx) {
                float2 t = shDxy[idx];
                float  z = shDz[idx];
                float  v = fmaf(ax, t.x, fmaf(ay, t.y, z));
                mn = fminf(mn, v);
            }
        }
        float m2 = q2 + mn;                        // upper bound on true min d^2
        #pragma unroll
        for (int o = 16; o > 0; o >>= 1)
            m2 = fmaxf(m2, __shfl_xor_sync(0xFFFFFFFF, m2, o));

        int rb = NBINS;                            // fallback: scan everything
        if (m2 < INFINITY)
            rb = (int)(sqrtf(fmaxf(m2, 0.0f)) * inv) + 2;

        // Phase 2: exact covering window, warp-uniform, 4-way min chains
        const int lo = offD[max(bl - rb, 0)];
        const int hi = offD[min(bh + rb, NBINS - 1) + 1];
        float mn0 = INFINITY, mn1 = INFINITY, mn2a = INFINITY, mn3 = INFINITY;
        int idx = lo;
        for (; idx + 4 <= hi; idx += 4) {
            float2 t0 = shDxy[idx];     float z0 = shDz[idx];
            float2 t1 = shDxy[idx + 1]; float z1 = shDz[idx + 1];
            float2 t2 = shDxy[idx + 2]; float z2 = shDz[idx + 2];
            float2 t3 = shDxy[idx + 3]; float z3 = shDz[idx + 3];
            mn0 = fminf(mn0, fmaf(ax, t0.x, fmaf(ay, t0.y, z0)));
            mn1 = fminf(mn1, fmaf(ax, t1.x, fmaf(ay, t1.y, z1)));
            mn2a = fminf(mn2a, fmaf(ax, t2.x, fmaf(ay, t2.y, z2)));
            mn3 = fminf(mn3, fmaf(ax, t3.x, fmaf(ay, t3.y, z3)));
        }
        for (; idx < hi; ++idx) {
            float2 t = shDxy[idx];
            mn0 = fminf(mn0, fmaf(ax, t.x, fmaf(ay, t.y, shDz[idx])));
        }
        float mfin = fminf(fminf(mn0, mn1), fminf(mn2a, mn3));

        // Stash result in this query's own slot (each slot read exactly once).
        shQ[qs].x = sqrtf(fmaxf(q2 + mfin, 0.0f));
    }
    __syncthreads();

    // ---- Scatter results to original order, then fixed-order sum ----
    float* rslt = (float*)shDxy;
    #pragma unroll
    for (int r = 0; r < EPT; ++r) {
        int j = r * THREADS + tid;
        rslt[shQi[j]] = shQ[j].x;
    }
    __syncthreads();

    float s = 0.0f;
    #pragma unroll
    for (int r = 0; r < EPT; ++r)
        s += rslt[tid + r * THREADS];

    red[tid] = s; __syncthreads();
    for (int o = THREADS / 2; o >= 32; o >>= 1) {
        if (tid < o) red[tid] += red[tid + o];
        __syncthreads();
    }
    float v = 0.0f;
    if (tid < 32) {
        v = red[tid];
        #pragma unroll
        for (int o = 16; o > 0; o >>= 1)
            v += __shfl_down_sync(0xFFFFFFFF, v, o);
    }

    // ---- Fused finalize: last block sums partials ----
    if (tid == 0) {
        g_partials[bx] = v;
        __threadfence();
        unsigned old = atomicAdd(&g_count, 1u);
        lastflag = (old == NBLOCKS - 1);
    }
    __syncthreads();
    if (lastflag && tid < 32) {
        volatile float* gp = g_partials;
        float t = 0.0f;
        #pragma unroll
        for (int i = 0; i < NBLOCKS / 32; ++i)
            t += gp[i * 32 + tid];
        #pragma unroll
        for (int o = 16; o > 0; o >>= 1)
            t += __shfl_down_sync(0xFFFFFFFF, t, o);
        if (tid == 0) {
            out[0] = t * (1.0f / ((float)K * (float)BATCH));
            g_count = 0;    // reset for next graph replay
        }
    }
}

extern "C" void kernel_launch(void* const* d_in, const int* in_sizes, int n_in,
                              void* d_out, int out_size)
{
    const float* pred = (const float*)d_in[0];
    const float* targ = (const float*)d_in[1];
    float* out = (float*)d_out;

    chamfer_nn_kernel<<<NBLOCKS, THREADS>>>(pred, targ, out);
}

// round 5
// speedup vs baseline: 3.1981x; 1.9610x over previous
#include <cuda_runtime.h>
#include <math.h>
#include <stdint.h>

// ChamferLoss via exact pruned NN, warp-uniform windows, v2.
// batch=64, k=2048 2-D points (x = cols [0,2048), y = cols [2048,4096)).
// One block per (batch, dir): counting-sort both sides by x (128 buckets).
// Each warp takes 32 consecutive sorted queries; phase-1 scans the warp's
// bucket neighborhood (broadcast LDS.128) for an upper bound; phase-2 scans
// only the left/right window extensions. Exact: min over a proven covering
// superset == brute-force min (fminf is order-independent). Deterministic:
// results written by original index, fixed-order sums, fused finalize.

#define K        2048
#define BATCH    64
#define THREADS  512
#define EPT      4             // 512*4 = 2048
#define NBINS    128
#define NBLOCKS  (2 * BATCH)

#define SMEM_D_BYTES   (K * 16)             // float4 per point: 32 KB
#define SMEM_Q_BYTES   (K * 8)              // float2 per query: 16 KB
#define SMEM_QI_BYTES  (K * 2)              // short index:       4 KB
#define DYN_SMEM       (SMEM_D_BYTES + SMEM_Q_BYTES + SMEM_QI_BYTES)

__device__ float g_partials[NBLOCKS];
__device__ unsigned int g_count = 0;

__global__ __launch_bounds__(THREADS, 1)
void chamfer_nn_kernel(const float* __restrict__ pred,
                       const float* __restrict__ targ,
                       float* __restrict__ out)
{
    extern __shared__ unsigned char dynsmem[];
    float4* shD  = (float4*)dynsmem;                              // sorted DB (x,y,z,0)
    float2* shQ  = (float2*)(dynsmem + SMEM_D_BYTES);             // sorted queries
    short*  shQi = (short*)(dynsmem + SMEM_D_BYTES + SMEM_Q_BYTES);

    __shared__ int   cntD[NBINS], cntQ[NBINS];     // histogram -> scatter cursors
    __shared__ int   offD[NBINS + 1];
    __shared__ float red[THREADS];
    __shared__ int   lastflag;

    const int bx    = blockIdx.x;
    const int batch = bx >> 1;
    const int dir   = bx & 1;
    const int tid   = threadIdx.x;

    const float* q_base = (dir == 0 ? pred : targ) + batch * (2 * K);
    const float* d_base = (dir == 0 ? targ : pred) + batch * (2 * K);

    // ---- Load both sides (coalesced); x min/max over BOTH sides ----
    float Dx[EPT], Dy[EPT], Qx[EPT], Qy[EPT];
    float lmin = INFINITY, lmax = -INFINITY;
    #pragma unroll
    for (int r = 0; r < EPT; ++r) {
        int j = r * THREADS + tid;
        Dx[r] = d_base[j];  Dy[r] = d_base[j + K];
        Qx[r] = q_base[j];  Qy[r] = q_base[j + K];
        lmin = fminf(lmin, fminf(Dx[r], Qx[r]));
        lmax = fmaxf(lmax, fmaxf(Dx[r], Qx[r]));
    }
    red[tid] = lmin; __syncthreads();
    for (int o = THREADS / 2; o > 0; o >>= 1) {
        if (tid < o) red[tid] = fminf(red[tid], red[tid + o]);
        __syncthreads();
    }
    const float xmin = red[0]; __syncthreads();
    red[tid] = lmax; __syncthreads();
    for (int o = THREADS / 2; o > 0; o >>= 1) {
        if (tid < o) red[tid] = fmaxf(red[tid], red[tid + o]);
        __syncthreads();
    }
    const float xmax = red[0]; __syncthreads();

    const float inv = (float)NBINS / ((xmax - xmin) * 1.000001f + 1e-30f);

    // ---- Histograms ----
    if (tid < NBINS) { cntD[tid] = 0; cntQ[tid] = 0; }
    __syncthreads();
    int bD[EPT], bQ[EPT];
    #pragma unroll
    for (int r = 0; r < EPT; ++r) {
        int b = (int)((Dx[r] - xmin) * inv);
        bD[r] = min(NBINS - 1, max(0, b));
        atomicAdd(&cntD[bD[r]], 1);
        b = (int)((Qx[r] - xmin) * inv);
        bQ[r] = min(NBINS - 1, max(0, b));
        atomicAdd(&cntQ[bQ[r]], 1);
    }
    __syncthreads();

    // ---- Exclusive prefix (warp 0: D -> offD + cursors; warp 1: Q -> cursors) ----
    int warp = tid >> 5, lane = tid & 31;
    if (warp < 2) {
        int* cnt = (warp == 0) ? cntD : cntQ;
        int c0 = cnt[lane * 4 + 0], c1 = cnt[lane * 4 + 1];
        int c2 = cnt[lane * 4 + 2], c3 = cnt[lane * 4 + 3];
        int s = c0 + c1 + c2 + c3, e = s;
        #pragma unroll
        for (int o = 1; o < 32; o <<= 1) {
            int n = __shfl_up_sync(0xFFFFFFFF, e, o);
            if (lane >= o) e += n;
        }
        int excl = e - s;
        if (warp == 0) {
            offD[lane * 4 + 0] = excl;
            offD[lane * 4 + 1] = excl + c0;
            offD[lane * 4 + 2] = excl + c0 + c1;
            offD[lane * 4 + 3] = excl + c0 + c1 + c2;
            if (lane == 31) offD[NBINS] = e;
        }
        cnt[lane * 4 + 0] = excl;
        cnt[lane * 4 + 1] = excl + c0;
        cnt[lane * 4 + 2] = excl + c0 + c1;
        cnt[lane * 4 + 3] = excl + c0 + c1 + c2;
    }
    __syncthreads();

    // ---- Scatter into bucket order ----
    #pragma unroll
    for (int r = 0; r < EPT; ++r) {
        int p = atomicAdd(&cntD[bD[r]], 1);
        shD[p] = make_float4(Dx[r], Dy[r], fmaf(Dx[r], Dx[r], Dy[r] * Dy[r]), 0.0f);
        p = atomicAdd(&cntQ[bQ[r]], 1);
        shQ[p]  = make_float2(Qx[r], Qy[r]);
        shQi[p] = (short)(r * THREADS + tid);
    }
    __syncthreads();

    // ---- Each warp: 32 consecutive sorted queries per chunk ----
    float result[EPT];
    #pragma unroll
    for (int c = 0; c < EPT; ++c) {
        const int qs = c * THREADS + tid;
        const float2 q = shQ[qs];
        const float ax = -2.0f * q.x;
        const float ay = -2.0f * q.y;
        const float q2 = fmaf(q.x, q.x, q.y * q.y);

        int b = min(NBINS - 1, max(0, (int)((q.x - xmin) * inv)));
        int bl = b, bh = b;
        #pragma unroll
        for (int o = 16; o > 0; o >>= 1) {
            bl = min(bl, __shfl_xor_sync(0xFFFFFFFF, bl, o));
            bh = max(bh, __shfl_xor_sync(0xFFFFFFFF, bh, o));
        }
        const int p1l = max(bl - 1, 0);
        const int p1h = min(bh + 1, NBINS - 1);

        // Phase 1: warp-uniform neighborhood scan (broadcast LDS.128)
        float mn0 = INFINITY, mn1 = INFINITY, mn2 = INFINITY, mn3 = INFINITY;
        {
            const int lo = offD[p1l], hi = offD[p1h + 1];
            int idx = lo;
            for (; idx + 4 <= hi; idx += 4) {
                float4 t0 = shD[idx], t1 = shD[idx + 1];
                float4 t2 = shD[idx + 2], t3 = shD[idx + 3];
                mn0 = fminf(mn0, fmaf(ax, t0.x, fmaf(ay, t0.y, t0.z)));
                mn1 = fminf(mn1, fmaf(ax, t1.x, fmaf(ay, t1.y, t1.z)));
                mn2 = fminf(mn2, fmaf(ax, t2.x, fmaf(ay, t2.y, t2.z)));
                mn3 = fminf(mn3, fmaf(ax, t3.x, fmaf(ay, t3.y, t3.z)));
            }
            for (; idx < hi; ++idx) {
                float4 t = shD[idx];
                mn0 = fminf(mn0, fmaf(ax, t.x, fmaf(ay, t.y, t.z)));
            }
        }
        float mn = fminf(fminf(mn0, mn1), fminf(mn2, mn3));

        // Warp-max upper bound -> exact covering radius in buckets
        float m2 = q2 + mn;
        #pragma unroll
        for (int o = 16; o > 0; o >>= 1)
            m2 = fmaxf(m2, __shfl_xor_sync(0xFFFFFFFF, m2, o));
        int rb = NBINS;
        if (m2 < INFINITY)
            rb = (int)(sqrtf(fmaxf(m2, 0.0f)) * inv) + 2;

        // Phase 2: scan only the extensions [bl-rb, p1l) and (p1h, bh+rb]
        const int loL = offD[max(bl - rb, 0)], hiL = offD[p1l];
        const int loR = offD[min(p1h + 1, NBINS)], hiR = offD[min(bh + rb, NBINS - 1) + 1];
        #pragma unroll
        for (int seg = 0; seg < 2; ++seg) {
            int idx = (seg == 0) ? loL : loR;
            const int hi = (seg == 0) ? hiL : hiR;
            for (; idx + 4 <= hi; idx += 4) {
                float4 t0 = shD[idx], t1 = shD[idx + 1];
                float4 t2 = shD[idx + 2], t3 = shD[idx + 3];
                mn0 = fminf(mn0, fmaf(ax, t0.x, fmaf(ay, t0.y, t0.z)));
                mn1 = fminf(mn1, fmaf(ax, t1.x, fmaf(ay, t1.y, t1.z)));
                mn2 = fminf(mn2, fmaf(ax, t2.x, fmaf(ay, t2.y, t2.z)));
                mn3 = fminf(mn3, fmaf(ax, t3.x, fmaf(ay, t3.y, t3.z)));
            }
            for (; idx < hi; ++idx) {
                float4 t = shD[idx];
                mn0 = fminf(mn0, fmaf(ax, t.x, fmaf(ay, t.y, t.z)));
            }
        }
        mn = fminf(fminf(mn0, mn1), fminf(mn2, mn3));
        result[c] = sqrtf(fmaxf(q2 + mn, 0.0f));
    }
    __syncthreads();

    // ---- Scatter results to original order (reuse shD), fixed-order sum ----
    float* rslt = (float*)shD;
    #pragma unroll
    for (int c = 0; c < EPT; ++c)
        rslt[shQi[c * THREADS + tid]] = result[c];
    __syncthreads();

    float s = 0.0f;
    #pragma unroll
    for (int r = 0; r < EPT; ++r)
        s += rslt[tid + r * THREADS];

    red[tid] = s; __syncthreads();
    for (int o = THREADS / 2; o >= 32; o >>= 1) {
        if (tid < o) red[tid] += red[tid + o];
        __syncthreads();
    }
    float v = 0.0f;
    if (tid < 32) {
        v = red[tid];
        #pragma unroll
        for (int o = 16; o > 0; o >>= 1)
            v += __shfl_down_sync(0xFFFFFFFF, v, o);
    }

    // ---- Fused finalize: last block sums the 128 partials ----
    if (tid == 0) {
        g_partials[bx] = v;
        __threadfence();
        unsigned old = atomicAdd(&g_count, 1u);
        lastflag = (old == NBLOCKS - 1);
    }
    __syncthreads();
    if (lastflag && tid < 32) {
        volatile float* gp = g_partials;
        float t = 0.0f;
        #pragma unroll
        for (int i = 0; i < NBLOCKS / 32; ++i)
            t += gp[i * 32 + tid];
        #pragma unroll
        for (int o = 16; o > 0; o >>= 1)
            t += __shfl_down_sync(0xFFFFFFFF, t, o);
        if (tid == 0) {
            out[0] = t * (1.0f / ((float)K * (float)BATCH));
            g_count = 0;   // reset for next graph replay
        }
    }
}

extern "C" void kernel_launch(void* const* d_in, const int* in_sizes, int n_in,
                              void* d_out, int out_size)
{
    const float* pred = (const float*)d_in[0];
    const float* targ = (const float*)d_in[1];
    float* out = (float*)d_out;

    cudaFuncSetAttribute(chamfer_nn_kernel,
                         cudaFuncAttributeMaxDynamicSharedMemorySize, DYN_SMEM);
    chamfer_nn_kernel<<<NBLOCKS, THREADS, DYN_SMEM>>>(pred, targ, out);
}

// round 6
// speedup vs baseline: 3.2848x; 1.0271x over previous
#include <cuda_runtime.h>
#include <math.h>
#include <stdint.h>

// ChamferLoss via exact pruned NN, warp-uniform windows, v3 (1024 thr/block).
// batch=64, k=2048 2-D points (x = cols [0,2048), y = cols [2048,4096)).
// One block per (batch, dir): counting-sort both sides by x (128 buckets).
// Each warp takes 32 consecutive sorted queries; phase-1 scans the warp's
// bucket neighborhood (broadcast LDS.128) for an upper bound; phase-2 scans
// only the left/right window extensions. Exact (min over proven covering
// superset). Deterministic: results by original index, fixed-order sums.

#define K        2048
#define BATCH    64
#define THREADS  1024
#define EPT      2             // 1024*2 = 2048
#define NBINS    128
#define NBLOCKS  (2 * BATCH)

#define SMEM_D_BYTES   (K * 16)             // float4 per point: 32 KB
#define SMEM_Q_BYTES   (K * 8)              // float2 per query: 16 KB
#define SMEM_QI_BYTES  (K * 2)              // short index:       4 KB
#define DYN_SMEM       (SMEM_D_BYTES + SMEM_Q_BYTES + SMEM_QI_BYTES)

__device__ float g_partials[NBLOCKS];
__device__ unsigned int g_count = 0;

__global__ __launch_bounds__(THREADS, 1)
void chamfer_nn_kernel(const float* __restrict__ pred,
                       const float* __restrict__ targ,
                       float* __restrict__ out)
{
    extern __shared__ unsigned char dynsmem[];
    float4* shD  = (float4*)dynsmem;                              // sorted DB (x,y,z,0)
    float2* shQ  = (float2*)(dynsmem + SMEM_D_BYTES);             // sorted queries
    short*  shQi = (short*)(dynsmem + SMEM_D_BYTES + SMEM_Q_BYTES);

    __shared__ int   cntD[NBINS], cntQ[NBINS];     // histogram -> scatter cursors
    __shared__ int   offD[NBINS + 1];
    __shared__ float red[THREADS];
    __shared__ int   lastflag;

    const int bx    = blockIdx.x;
    const int batch = bx >> 1;
    const int dir   = bx & 1;
    const int tid   = threadIdx.x;

    const float* q_base = (dir == 0 ? pred : targ) + batch * (2 * K);
    const float* d_base = (dir == 0 ? targ : pred) + batch * (2 * K);

    // ---- Load both sides (coalesced); x min/max over BOTH sides ----
    float Dx[EPT], Dy[EPT], Qx[EPT], Qy[EPT];
    float lmin = INFINITY, lmax = -INFINITY;
    #pragma unroll
    for (int r = 0; r < EPT; ++r) {
        int j = r * THREADS + tid;
        Dx[r] = d_base[j];  Dy[r] = d_base[j + K];
        Qx[r] = q_base[j];  Qy[r] = q_base[j + K];
        lmin = fminf(lmin, fminf(Dx[r], Qx[r]));
        lmax = fmaxf(lmax, fmaxf(Dx[r], Qx[r]));
    }
    red[tid] = lmin; __syncthreads();
    for (int o = THREADS / 2; o > 0; o >>= 1) {
        if (tid < o) red[tid] = fminf(red[tid], red[tid + o]);
        __syncthreads();
    }
    const float xmin = red[0]; __syncthreads();
    red[tid] = lmax; __syncthreads();
    for (int o = THREADS / 2; o > 0; o >>= 1) {
        if (tid < o) red[tid] = fmaxf(red[tid], red[tid + o]);
        __syncthreads();
    }
    const float xmax = red[0]; __syncthreads();

    const float inv = (float)NBINS / ((xmax - xmin) * 1.000001f + 1e-30f);

    // ---- Histograms ----
    if (tid < NBINS) { cntD[tid] = 0; cntQ[tid] = 0; }
    __syncthreads();
    int bD[EPT], bQ[EPT];
    #pragma unroll
    for (int r = 0; r < EPT; ++r) {
        int b = (int)((Dx[r] - xmin) * inv);
        bD[r] = min(NBINS - 1, max(0, b));
        atomicAdd(&cntD[bD[r]], 1);
        b = (int)((Qx[r] - xmin) * inv);
        bQ[r] = min(NBINS - 1, max(0, b));
        atomicAdd(&cntQ[bQ[r]], 1);
    }
    __syncthreads();

    // ---- Exclusive prefix (warp 0: D -> offD + cursors; warp 1: Q -> cursors) ----
    int warp = tid >> 5, lane = tid & 31;
    if (warp < 2) {
        int* cnt = (warp == 0) ? cntD : cntQ;
        int c0 = cnt[lane * 4 + 0], c1 = cnt[lane * 4 + 1];
        int c2 = cnt[lane * 4 + 2], c3 = cnt[lane * 4 + 3];
        int s = c0 + c1 + c2 + c3, e = s;
        #pragma unroll
        for (int o = 1; o < 32; o <<= 1) {
            int n = __shfl_up_sync(0xFFFFFFFF, e, o);
            if (lane >= o) e += n;
        }
        int excl = e - s;
        if (warp == 0) {
            offD[lane * 4 + 0] = excl;
            offD[lane * 4 + 1] = excl + c0;
            offD[lane * 4 + 2] = excl + c0 + c1;
            offD[lane * 4 + 3] = excl + c0 + c1 + c2;
            if (lane == 31) offD[NBINS] = e;
        }
        cnt[lane * 4 + 0] = excl;
        cnt[lane * 4 + 1] = excl + c0;
        cnt[lane * 4 + 2] = excl + c0 + c1;
        cnt[lane * 4 + 3] = excl + c0 + c1 + c2;
    }
    __syncthreads();

    // ---- Scatter into bucket order ----
    #pragma unroll
    for (int r = 0; r < EPT; ++r) {
        int p = atomicAdd(&cntD[bD[r]], 1);
        shD[p] = make_float4(Dx[r], Dy[r], fmaf(Dx[r], Dx[r], Dy[r] * Dy[r]), 0.0f);
        p = atomicAdd(&cntQ[bQ[r]], 1);
        shQ[p]  = make_float2(Qx[r], Qy[r]);
        shQi[p] = (short)(r * THREADS + tid);
    }
    __syncthreads();

    // ---- Each warp: 32 consecutive sorted queries per chunk ----
    float result[EPT];
    #pragma unroll
    for (int c = 0; c < EPT; ++c) {
        const int qs = c * THREADS + tid;
        const float2 q = shQ[qs];
        const float ax = -2.0f * q.x;
        const float ay = -2.0f * q.y;
        const float q2 = fmaf(q.x, q.x, q.y * q.y);

        int b = min(NBINS - 1, max(0, (int)((q.x - xmin) * inv)));
        const int bl = __reduce_min_sync(0xFFFFFFFF, b);
        const int bh = __reduce_max_sync(0xFFFFFFFF, b);
        const int p1l = max(bl - 1, 0);
        const int p1h = min(bh + 1, NBINS - 1);

        // Phase 1: warp-uniform neighborhood scan (broadcast LDS.128)
        float mn0 = INFINITY, mn1 = INFINITY, mn2 = INFINITY, mn3 = INFINITY;
        {
            const int lo = offD[p1l], hi = offD[p1h + 1];
            int idx = lo;
            for (; idx + 4 <= hi; idx += 4) {
                float4 t0 = shD[idx], t1 = shD[idx + 1];
                float4 t2 = shD[idx + 2], t3 = shD[idx + 3];
                mn0 = fminf(mn0, fmaf(ax, t0.x, fmaf(ay, t0.y, t0.z)));
                mn1 = fminf(mn1, fmaf(ax, t1.x, fmaf(ay, t1.y, t1.z)));
                mn2 = fminf(mn2, fmaf(ax, t2.x, fmaf(ay, t2.y, t2.z)));
                mn3 = fminf(mn3, fmaf(ax, t3.x, fmaf(ay, t3.y, t3.z)));
            }
            for (; idx < hi; ++idx) {
                float4 t = shD[idx];
                mn0 = fminf(mn0, fmaf(ax, t.x, fmaf(ay, t.y, t.z)));
            }
        }
        float mn = fminf(fminf(mn0, mn1), fminf(mn2, mn3));

        // Warp-max upper bound -> exact covering radius in buckets.
        // Clamp to >= 0 so the float bit pattern is order-preserving as int.
        float m2c = fmaxf(q2 + mn, 0.0f);
        int m2i = __reduce_max_sync(0xFFFFFFFF, __float_as_int(m2c));
        float m2 = __int_as_float(m2i);
        int rb = NBINS;
        if (m2 < INFINITY)
            rb = (int)(sqrtf(m2) * inv) + 2;

        // Phase 2: scan only the extensions [bl-rb, p1l) and (p1h, bh+rb]
        const int loL = offD[max(bl - rb, 0)], hiL = offD[p1l];
        const int loR = offD[min(p1h + 1, NBINS)], hiR = offD[min(bh + rb, NBINS - 1) + 1];
        #pragma unroll
        for (int seg = 0; seg < 2; ++seg) {
            int idx = (seg == 0) ? loL : loR;
            const int hi = (seg == 0) ? hiL : hiR;
            for (; idx + 4 <= hi; idx += 4) {
                float4 t0 = shD[idx], t1 = shD[idx + 1];
                float4 t2 = shD[idx + 2], t3 = shD[idx + 3];
                mn0 = fminf(mn0, fmaf(ax, t0.x, fmaf(ay, t0.y, t0.z)));
                mn1 = fminf(mn1, fmaf(ax, t1.x, fmaf(ay, t1.y, t1.z)));
                mn2 = fminf(mn2, fmaf(ax, t2.x, fmaf(ay, t2.y, t2.z)));
                mn3 = fminf(mn3, fmaf(ax, t3.x, fmaf(ay, t3.y, t3.z)));
            }
            for (; idx < hi; ++idx) {
                float4 t = shD[idx];
                mn0 = fminf(mn0, fmaf(ax, t.x, fmaf(ay, t.y, t.z)));
            }
        }
        mn = fminf(fminf(mn0, mn1), fminf(mn2, mn3));
        result[c] = sqrtf(fmaxf(q2 + mn, 0.0f));
    }
    __syncthreads();

    // ---- Scatter results to original order (reuse shD), fixed-order sum ----
    float* rslt = (float*)shD;
    #pragma unroll
    for (int c = 0; c < EPT; ++c)
        rslt[shQi[c * THREADS + tid]] = result[c];
    __syncthreads();

    float s = 0.0f;
    #pragma unroll
    for (int r = 0; r < EPT; ++r)
        s += rslt[tid + r * THREADS];

    red[tid] = s; __syncthreads();
    for (int o = THREADS / 2; o >= 32; o >>= 1) {
        if (tid < o) red[tid] += red[tid + o];
        __syncthreads();
    }
    float v = 0.0f;
    if (tid < 32) {
        v = red[tid];
        #pragma unroll
        for (int o = 16; o > 0; o >>= 1)
            v += __shfl_down_sync(0xFFFFFFFF, v, o);
    }

    // ---- Fused finalize: last block sums the 128 partials ----
    if (tid == 0) {
        g_partials[bx] = v;
        __threadfence();
        unsigned old = atomicAdd(&g_count, 1u);
        lastflag = (old == NBLOCKS - 1);
    }
    __syncthreads();
    if (lastflag && tid < 32) {
        volatile float* gp = g_partials;
        float t = 0.0f;
        #pragma unroll
        for (int i = 0; i < NBLOCKS / 32; ++i)
            t += gp[i * 32 + tid];
        #pragma unroll
        for (int o = 16; o > 0; o >>= 1)
            t += __shfl_down_sync(0xFFFFFFFF, t, o);
        if (tid == 0) {
            out[0] = t * (1.0f / ((float)K * (float)BATCH));
            g_count = 0;   // reset for next graph replay
        }
    }
}

extern "C" void kernel_launch(void* const* d_in, const int* in_sizes, int n_in,
                              void* d_out, int out_size)
{
    const float* pred = (const float*)d_in[0];
    const float* targ = (const float*)d_in[1];
    float* out = (float*)d_out;

    cudaFuncSetAttribute(chamfer_nn_kernel,
                         cudaFuncAttributeMaxDynamicSharedMemorySize, DYN_SMEM);
    chamfer_nn_kernel<<<NBLOCKS, THREADS, DYN_SMEM>>>(pred, targ, out);
}

// round 7
// speedup vs baseline: 4.3282x; 1.3176x over previous
#include <cuda_runtime.h>
#include <math.h>
#include <stdint.h>

// ChamferLoss via exact pruned NN, v4: 64 queries/warp (2 per lane),
// vote-based exact window expansion (no radius rescan).
// batch=64, k=2048 2-D points (x = cols [0,2048), y = cols [2048,4096)).
// One 1024-thread block per (batch, dir): counting-sort both sides by x into
// 128 buckets. Each warp owns 64 consecutive sorted queries; phase-1 scans the
// group's bucket neighborhood (broadcast LDS.128, each candidate serves the
// lane's 2 queries); then buckets are consumed outward left/right with a warp
// vote per bucket until no lane can improve. Exact == brute force (min over a
// proven covering superset). Deterministic: results written by original index,
// fixed-order sums, fused last-block finalize.

#define K        2048
#define BATCH    64
#define THREADS  1024
#define NWARPS   (THREADS / 32)
#define NBINS    128
#define NBLOCKS  (2 * BATCH)

#define SMEM_D_BYTES   (K * 16)             // float4 per point: 32 KB
#define SMEM_Q_BYTES   (K * 8)              // float2 per query: 16 KB
#define SMEM_QI_BYTES  (K * 2)              // short index:       4 KB
#define DYN_SMEM       (SMEM_D_BYTES + SMEM_Q_BYTES + SMEM_QI_BYTES)

__device__ float g_partials[NBLOCKS];
__device__ unsigned int g_count = 0;

__global__ __launch_bounds__(THREADS, 1)
void chamfer_nn_kernel(const float* __restrict__ pred,
                       const float* __restrict__ targ,
                       float* __restrict__ out)
{
    extern __shared__ unsigned char dynsmem[];
    float4* shD  = (float4*)dynsmem;                              // sorted DB (x,y,z,0)
    float2* shQ  = (float2*)(dynsmem + SMEM_D_BYTES);             // sorted queries
    short*  shQi = (short*)(dynsmem + SMEM_D_BYTES + SMEM_Q_BYTES);

    __shared__ int   cntD[NBINS], cntQ[NBINS];     // histogram -> scatter cursors
    __shared__ int   offD[NBINS + 1];
    __shared__ float redA[NWARPS], redB[NWARPS];
    __shared__ int   lastflag;

    const int bx    = blockIdx.x;
    const int batch = bx >> 1;
    const int dir   = bx & 1;
    const int tid   = threadIdx.x;
    const int wg    = tid >> 5;
    const int lane  = tid & 31;

    const float* q_base = (dir == 0 ? pred : targ) + batch * (2 * K);
    const float* d_base = (dir == 0 ? targ : pred) + batch * (2 * K);

    // ---- Load both sides (coalesced); x min/max over BOTH sides ----
    float Dx0 = d_base[tid],            Dy0 = d_base[tid + K];
    float Dx1 = d_base[tid + THREADS],  Dy1 = d_base[tid + THREADS + K];
    float Qx0 = q_base[tid],            Qy0 = q_base[tid + K];
    float Qx1 = q_base[tid + THREADS],  Qy1 = q_base[tid + THREADS + K];

    float lmin = fminf(fminf(Dx0, Dx1), fminf(Qx0, Qx1));
    float lmax = fmaxf(fmaxf(Dx0, Dx1), fmaxf(Qx0, Qx1));
    #pragma unroll
    for (int o = 16; o > 0; o >>= 1) {
        lmin = fminf(lmin, __shfl_xor_sync(0xFFFFFFFF, lmin, o));
        lmax = fmaxf(lmax, __shfl_xor_sync(0xFFFFFFFF, lmax, o));
    }
    if (lane == 0) { redA[wg] = lmin; redB[wg] = lmax; }
    __syncthreads();
    if (tid < 32) {
        float a = redA[tid], b = redB[tid];
        #pragma unroll
        for (int o = 16; o > 0; o >>= 1) {
            a = fminf(a, __shfl_xor_sync(0xFFFFFFFF, a, o));
            b = fmaxf(b, __shfl_xor_sync(0xFFFFFFFF, b, o));
        }
        if (tid == 0) { redA[0] = a; redB[0] = b; }
    }
    __syncthreads();
    const float xmin = redA[0];
    const float xmax = redB[0];
    const float inv  = (float)NBINS / ((xmax - xmin) * 1.000001f + 1e-30f);
    const float w    = 1.0f / inv;
    __syncthreads();          // redA/redB reuse below

    // ---- Histograms ----
    if (tid < NBINS) { cntD[tid] = 0; cntQ[tid] = 0; }
    __syncthreads();
    int bD0 = min(NBINS - 1, max(0, (int)((Dx0 - xmin) * inv)));
    int bD1 = min(NBINS - 1, max(0, (int)((Dx1 - xmin) * inv)));
    int bQ0 = min(NBINS - 1, max(0, (int)((Qx0 - xmin) * inv)));
    int bQ1 = min(NBINS - 1, max(0, (int)((Qx1 - xmin) * inv)));
    atomicAdd(&cntD[bD0], 1); atomicAdd(&cntD[bD1], 1);
    atomicAdd(&cntQ[bQ0], 1); atomicAdd(&cntQ[bQ1], 1);
    __syncthreads();

    // ---- Exclusive prefix (warp 0: D -> offD + cursors; warp 1: Q -> cursors) ----
    if (wg < 2) {
        int* cnt = (wg == 0) ? cntD : cntQ;
        int c0 = cnt[lane * 4 + 0], c1 = cnt[lane * 4 + 1];
        int c2 = cnt[lane * 4 + 2], c3 = cnt[lane * 4 + 3];
        int s = c0 + c1 + c2 + c3, e = s;
        #pragma unroll
        for (int o = 1; o < 32; o <<= 1) {
            int n = __shfl_up_sync(0xFFFFFFFF, e, o);
            if (lane >= o) e += n;
        }
        int excl = e - s;
        if (wg == 0) {
            offD[lane * 4 + 0] = excl;
            offD[lane * 4 + 1] = excl + c0;
            offD[lane * 4 + 2] = excl + c0 + c1;
            offD[lane * 4 + 3] = excl + c0 + c1 + c2;
            if (lane == 31) offD[NBINS] = e;
        }
        cnt[lane * 4 + 0] = excl;
        cnt[lane * 4 + 1] = excl + c0;
        cnt[lane * 4 + 2] = excl + c0 + c1;
        cnt[lane * 4 + 3] = excl + c0 + c1 + c2;
    }
    __syncthreads();

    // ---- Scatter into bucket order ----
    {
        int p = atomicAdd(&cntD[bD0], 1);
        shD[p] = make_float4(Dx0, Dy0, fmaf(Dx0, Dx0, Dy0 * Dy0), 0.0f);
        p = atomicAdd(&cntD[bD1], 1);
        shD[p] = make_float4(Dx1, Dy1, fmaf(Dx1, Dx1, Dy1 * Dy1), 0.0f);
        p = atomicAdd(&cntQ[bQ0], 1);
        shQ[p] = make_float2(Qx0, Qy0);  shQi[p] = (short)tid;
        p = atomicAdd(&cntQ[bQ1], 1);
        shQ[p] = make_float2(Qx1, Qy1);  shQi[p] = (short)(tid + THREADS);
    }
    __syncthreads();

    // ---- Each warp: 64 consecutive sorted queries, 2 per lane ----
    const float4 qq = ((const float4*)shQ)[wg * 32 + lane];  // queries 2i, 2i+1
    const float ax0 = -2.0f * qq.x, ay0 = -2.0f * qq.y;
    const float ax1 = -2.0f * qq.z, ay1 = -2.0f * qq.w;
    const float q20 = fmaf(qq.x, qq.x, qq.y * qq.y);
    const float q21 = fmaf(qq.z, qq.z, qq.w * qq.w);
    const float qxmn = fminf(qq.x, qq.z);
    const float qxmx = fmaxf(qq.x, qq.z);

    int b0 = min(NBINS - 1, max(0, (int)((qq.x - xmin) * inv)));
    int b1 = min(NBINS - 1, max(0, (int)((qq.z - xmin) * inv)));
    const int bl = __reduce_min_sync(0xFFFFFFFF, min(b0, b1));
    const int bh = __reduce_max_sync(0xFFFFFFFF, max(b0, b1));

    float mnA0 = INFINITY, mnB0 = INFINITY;   // query 0: two accumulator chains
    float mnA1 = INFINITY, mnB1 = INFINITY;   // query 1

    // Phase 1: contiguous neighborhood scan (broadcast LDS.128)
    {
        const int lo = offD[max(bl - 1, 0)];
        const int hi = offD[min(bh + 1, NBINS - 1) + 1];
        int idx = lo;
        for (; idx + 2 <= hi; idx += 2) {
            float4 t0 = shD[idx], t1 = shD[idx + 1];
            mnA0 = fminf(mnA0, fmaf(ax0, t0.x, fmaf(ay0, t0.y, t0.z)));
            mnA1 = fminf(mnA1, fmaf(ax1, t0.x, fmaf(ay1, t0.y, t0.z)));
            mnB0 = fminf(mnB0, fmaf(ax0, t1.x, fmaf(ay0, t1.y, t1.z)));
            mnB1 = fminf(mnB1, fmaf(ax1, t1.x, fmaf(ay1, t1.y, t1.z)));
        }
        if (idx < hi) {
            float4 t = shD[idx];
            mnA0 = fminf(mnA0, fmaf(ax0, t.x, fmaf(ay0, t.y, t.z)));
            mnA1 = fminf(mnA1, fmaf(ax1, t.x, fmaf(ay1, t.y, t.z)));
        }
    }

    // Left expansion: vote per bucket, stop when no lane can improve.
    for (int l = bl - 2; l >= 0; --l) {
        float best = fmaxf(q20 + fminf(mnA0, mnB0), q21 + fminf(mnA1, mnB1));
        float gap  = qxmn - (xmin + (float)(l + 1) * w);   // to bucket's right edge
        bool need  = (gap <= 0.0f) || (gap * gap < best);
        if (!__any_sync(0xFFFFFFFF, need)) break;
        const int lo = offD[l], hi = offD[l + 1];
        for (int idx = lo; idx < hi; ++idx) {
            float4 t = shD[idx];
            mnA0 = fminf(mnA0, fmaf(ax0, t.x, fmaf(ay0, t.y, t.z)));
            mnA1 = fminf(mnA1, fmaf(ax1, t.x, fmaf(ay1, t.y, t.z)));
        }
    }
    // Right expansion.
    for (int r = bh + 2; r < NBINS; ++r) {
        float best = fmaxf(q20 + fminf(mnA0, mnB0), q21 + fminf(mnA1, mnB1));
        float gap  = (xmin + (float)r * w) - qxmx;         // to bucket's left edge
        bool need  = (gap <= 0.0f) || (gap * gap < best);
        if (!__any_sync(0xFFFFFFFF, need)) break;
        const int lo = offD[r], hi = offD[r + 1];
        for (int idx = lo; idx < hi; ++idx) {
            float4 t = shD[idx];
            mnB0 = fminf(mnB0, fmaf(ax0, t.x, fmaf(ay0, t.y, t.z)));
            mnB1 = fminf(mnB1, fmaf(ax1, t.x, fmaf(ay1, t.y, t.z)));
        }
    }

    const float res0 = sqrtf(fmaxf(q20 + fminf(mnA0, mnB0), 0.0f));
    const float res1 = sqrtf(fmaxf(q21 + fminf(mnA1, mnB1), 0.0f));
    const int qi0 = wg * 64 + 2 * lane;
    __syncthreads();     // everyone done reading shD before overwrite

    // ---- Scatter results to original order (reuse shD), fixed-order sum ----
    float* rslt = (float*)shD;
    rslt[shQi[qi0]]     = res0;
    rslt[shQi[qi0 + 1]] = res1;
    __syncthreads();

    float s = rslt[tid] + rslt[tid + THREADS];
    #pragma unroll
    for (int o = 16; o > 0; o >>= 1)
        s += __shfl_xor_sync(0xFFFFFFFF, s, o);
    if (lane == 0) redA[wg] = s;
    __syncthreads();

    float v = 0.0f;
    if (tid < 32) {
        v = redA[tid];
        #pragma unroll
        for (int o = 16; o > 0; o >>= 1)
            v += __shfl_down_sync(0xFFFFFFFF, v, o);
    }

    // ---- Fused finalize: last block sums the 128 partials ----
    if (tid == 0) {
        g_partials[bx] = v;
        __threadfence();
        unsigned old = atomicAdd(&g_count, 1u);
        lastflag = (old == NBLOCKS - 1);
    }
    __syncthreads();
    if (lastflag && tid < 32) {
        volatile float* gp = g_partials;
        float t = 0.0f;
        #pragma unroll
        for (int i = 0; i < NBLOCKS / 32; ++i)
            t += gp[i * 32 + tid];
        #pragma unroll
        for (int o = 16; o > 0; o >>= 1)
            t += __shfl_down_sync(0xFFFFFFFF, t, o);
        if (tid == 0) {
            out[0] = t * (1.0f / ((float)K * (float)BATCH));
            g_count = 0;   // reset for next graph replay
        }
    }
}

extern "C" void kernel_launch(void* const* d_in, const int* in_sizes, int n_in,
                              void* d_out, int out_size)
{
    const float* pred = (const float*)d_in[0];
    const float* targ = (const float*)d_in[1];
    float* out = (float*)d_out;

    cudaFuncSetAttribute(chamfer_nn_kernel,
                         cudaFuncAttributeMaxDynamicSharedMemorySize, DYN_SMEM);
    chamfer_nn_kernel<<<NBLOCKS, THREADS, DYN_SMEM>>>(pred, targ, out);
}